// round 4
// baseline (speedup 1.0000x reference)
#include <cuda_runtime.h>
#include <cstdint>

#define T_LEN 6000
#define BATCH 64
#define HID   128
#define PROJ  32
#define G4    512   // 4*HID

typedef unsigned long long u64;

// ---------------- scratch ----------------
__device__ float g_xi[(size_t)T_LEN * BATCH * G4];   // layer0 input transform

// ---------------- f32x2 helpers ----------------
__device__ __forceinline__ u64 pk(float lo, float hi) {
    u64 r;
    asm("mov.b64 %0, {%1, %2};" : "=l"(r) : "f"(lo), "f"(hi));
    return r;
}
__device__ __forceinline__ void upk(u64 a, float& lo, float& hi) {
    asm("mov.b64 {%0, %1}, %2;" : "=f"(lo), "=f"(hi) : "l"(a));
}
__device__ __forceinline__ void fma2(u64& d, u64 a, u64 b) {
    asm("fma.rn.f32x2 %0, %1, %2, %3;" : "=l"(d) : "l"(a), "l"(b), "l"(d));
}
__device__ __forceinline__ u64 add2(u64 a, u64 b) {
    u64 r;
    asm("add.rn.f32x2 %0, %1, %2;" : "=l"(r) : "l"(a), "l"(b));
    return r;
}
__device__ __forceinline__ float hsum(u64 a) {
    float lo, hi; upk(a, lo, hi); return lo + hi;
}

// ---------------- fast activations ----------------
__device__ __forceinline__ float tanh_hw(float x) {          // MUFU.TANH
    float r; asm("tanh.approx.f32 %0, %1;" : "=f"(r) : "f"(x)); return r;
}
__device__ __forceinline__ float sigm(float x) {             // gate sigmoids
    return fmaf(tanh_hw(x * 0.5f), 0.5f, 0.5f);
}
__device__ __forceinline__ float ex2_(float x) {
    float r; asm("ex2.approx.f32 %0, %1;" : "=f"(r) : "f"(x)); return r;
}
__device__ __forceinline__ float rcp_(float x) {
    float r; asm("rcp.approx.f32 %0, %1;" : "=f"(r) : "f"(x)); return r;
}
__device__ __forceinline__ float tanh_acc(float x) {         // accurate tanh
    float e = ex2_(x * 2.8853900817779268f);                 // e^{2x}
    return fmaf(rcp_(1.f + e), -2.f, 1.f);
}
__device__ __forceinline__ float sigm_acc(float x) {         // final output sigmoid
    return rcp_(1.f + ex2_(-x * 1.4426950408889634f));
}

// ---------------- GEMM0 ----------------
__global__ void __launch_bounds__(512, 1) gemm_xi0(
    const float* __restrict__ x, const float* __restrict__ Wih,
    const float* __restrict__ bih, const float* __restrict__ bhh,
    float* __restrict__ xi)
{
    int b  = blockIdx.y;
    int t0 = blockIdx.x * 128;
    int g  = threadIdx.x;

    __shared__ u64 xs2[80][64];   // packed (t,t+1) pairs, 40KB

    for (int idx = g; idx < 80 * 32; idx += 512) {
        int f = idx >> 5, i4 = idx & 31;
        int t = t0 + i4 * 4;
        const float* src = x + ((size_t)b * 80 + f) * T_LEN + t;
        float4 v;
        if (t + 3 < T_LEN) {
            v = *reinterpret_cast<const float4*>(src);
        } else {
            v.x = (t     < T_LEN) ? src[0] : 0.f;
            v.y = (t + 1 < T_LEN) ? src[1] : 0.f;
            v.z = (t + 2 < T_LEN) ? src[2] : 0.f;
            v.w = (t + 3 < T_LEN) ? src[3] : 0.f;
        }
        xs2[f][i4 * 2]     = pk(v.x, v.y);
        xs2[f][i4 * 2 + 1] = pk(v.z, v.w);
    }

    float w[80];
#pragma unroll
    for (int f = 0; f < 80; f++) w[f] = Wih[g * 80 + f];
    float bias = bih[g] + bhh[g];
    __syncthreads();

    int tmax = min(128, T_LEN - t0);   // 128 or 112, both multiples of 8
    const size_t st = (size_t)BATCH * G4;

    for (int i8 = 0; i8 < tmax / 8; i8++) {
        u64 a0 = pk(bias, bias), a1 = a0, a2 = a0, a3 = a0;
#pragma unroll
        for (int f = 0; f < 80; f++) {
            u64 pA, pB, pC, pD;
            uint32_t sa = (uint32_t)__cvta_generic_to_shared(&xs2[f][i8 * 4]);
            asm("ld.shared.v2.u64 {%0, %1}, [%2];"    : "=l"(pA), "=l"(pB) : "r"(sa));
            asm("ld.shared.v2.u64 {%0, %1}, [%2+16];" : "=l"(pC), "=l"(pD) : "r"(sa));
            u64 w2 = pk(w[f], w[f]);
            fma2(a0, w2, pA); fma2(a1, w2, pB);
            fma2(a2, w2, pC); fma2(a3, w2, pD);
        }
        size_t o = ((size_t)(t0 + i8 * 8) * BATCH + b) * G4 + g;
        float lo, hi;
        upk(a0, lo, hi); xi[o]          = lo; xi[o + st]     = hi;
        upk(a1, lo, hi); xi[o + 2 * st] = lo; xi[o + 3 * st] = hi;
        upk(a2, lo, hi); xi[o + 4 * st] = lo; xi[o + 5 * st] = hi;
        upk(a3, lo, hi); xi[o + 6 * st] = lo; xi[o + 7 * st] = hi;
    }
}

// ---------------- fused scan shared state (dynamic smem, ~53KB) ----------------
struct ScanSmem {
    float h0ring[8][32];    // grp0 -> grp1
    float xi1ring[8][512];  // grp1 -> grp2
    float ot0s[128];
    float ot1s[128];
    float hp0[4][32];
    float hp1[4][32];
    float hb0[4][32];       // warp-private h0 copies
    float hb1[4][32];       // warp-private h1 copies
    u64 whr0s[4][16][32];   // [warp][pair][lane]
    u64 whr1s[4][16][32];
};

// ---------------- fused pipelined scan ----------------
// 384 threads / block, one block per batch element.
//   grp0 (warps 0-3):  layer-0 cells (lag 0)
//   grp1 (warps 4-7):  xi1 = Wih1*h0 + bias1   (lag 4)
//   grp2 (warps 8-11): layer-1 cells + head    (lag 8)
// Cross-group handoff through 8-deep rings; block barrier only every 4 steps.
__global__ void __launch_bounds__(384, 1) fused_scan(
    const float* __restrict__ xi0,
    const float* __restrict__ Whh0, const float* __restrict__ Whr0,
    const float* __restrict__ Wih1,
    const float* __restrict__ bih1, const float* __restrict__ bhh1,
    const float* __restrict__ Whh1, const float* __restrict__ Whr1,
    const float* __restrict__ W2,   const float* __restrict__ b2,
    float* __restrict__ out)
{
    extern __shared__ __align__(16) char smem_raw[];
    ScanSmem& S = *reinterpret_cast<ScanSmem*>(smem_raw);

    const int b   = blockIdx.x;
    const int tid = threadIdx.x;
    const int grp = tid >> 7;          // 0,1,2
    const int u   = tid & 127;
    const int w   = u >> 5, l = u & 31;

    u64   wgt[4][16];      // Whh0 / Wih1 / Whh1 rows, packed
    float bias1q[4];
    float c = 0.f;
    float w2v = 0.f, b2v = 0.f;

    if (grp == 0) {
#pragma unroll
        for (int q = 0; q < 4; q++) {
            const u64* p = reinterpret_cast<const u64*>(Whh0 + (q * HID + u) * PROJ);
#pragma unroll
            for (int j = 0; j < 16; j++) wgt[q][j] = p[j];
        }
        const u64* wr = reinterpret_cast<const u64*>(Whr0 + l * HID + w * 32);
#pragma unroll
        for (int i = 0; i < 16; i++) S.whr0s[w][i][l] = wr[i];
        S.hb0[w][l] = 0.f;
    } else if (grp == 1) {
#pragma unroll
        for (int q = 0; q < 4; q++) {
            const u64* p = reinterpret_cast<const u64*>(Wih1 + (q * HID + u) * PROJ);
#pragma unroll
            for (int j = 0; j < 16; j++) wgt[q][j] = p[j];
            bias1q[q] = bih1[q * HID + u] + bhh1[q * HID + u];
        }
    } else {
#pragma unroll
        for (int q = 0; q < 4; q++) {
            const u64* p = reinterpret_cast<const u64*>(Whh1 + (q * HID + u) * PROJ);
#pragma unroll
            for (int j = 0; j < 16; j++) wgt[q][j] = p[j];
        }
        const u64* wr = reinterpret_cast<const u64*>(Whr1 + l * HID + w * 32);
#pragma unroll
        for (int i = 0; i < 16; i++) S.whr1s[w][i][l] = wr[i];
        S.hb1[w][l] = 0.f;
        w2v = W2[l];
        b2v = b2[0];
    }
    __syncthreads();

    // grp0: 2-deep xi0 prefetch
    const size_t strideT = (size_t)BATCH * G4;
    const float* xp = xi0 + (size_t)b * G4 + u;
    float cur[4], nxt[4];
    if (grp == 0) {
#pragma unroll
        for (int q = 0; q < 4; q++) cur[q] = __ldcs(xp + q * HID);
#pragma unroll
        for (int q = 0; q < 4; q++) nxt[q] = __ldcs(xp + strideT + q * HID);
    }

    const int ITERS = T_LEN + 8;   // multiple of 4

    for (int i = 0; i < ITERS; i++) {
        if (grp == 0) {
            if (i < T_LEN) {
                const int s = i;
                float g0 = cur[0], g1 = cur[1], g2 = cur[2], g3 = cur[3];
#pragma unroll
                for (int q = 0; q < 4; q++) cur[q] = nxt[q];
                if (s + 2 < T_LEN) {
                    const float* xn = xp + (size_t)(s + 2) * strideT;
#pragma unroll
                    for (int q = 0; q < 4; q++) nxt[q] = __ldcs(xn + q * HID);
                }
                const u64* h2 = reinterpret_cast<const u64*>(S.hb0[w]);
                u64 aA0 = pk(0.f,0.f), aA1 = aA0, aA2 = aA0, aA3 = aA0;
                u64 aB0 = aA0, aB1 = aA0, aB2 = aA0, aB3 = aA0;
#pragma unroll
                for (int j = 0; j < 8; j++) {
                    u64 hv = h2[j];
                    fma2(aA0, wgt[0][j], hv); fma2(aA1, wgt[1][j], hv);
                    fma2(aA2, wgt[2][j], hv); fma2(aA3, wgt[3][j], hv);
                }
#pragma unroll
                for (int j = 8; j < 16; j++) {
                    u64 hv = h2[j];
                    fma2(aB0, wgt[0][j], hv); fma2(aB1, wgt[1][j], hv);
                    fma2(aB2, wgt[2][j], hv); fma2(aB3, wgt[3][j], hv);
                }
                g0 += hsum(add2(aA0, aB0));
                g1 += hsum(add2(aA1, aB1));
                g2 += hsum(add2(aA2, aB2));
                g3 += hsum(add2(aA3, aB3));

                float iv = sigm(g0), fv = sigm(g1);
                float gv = tanh_acc(g2), ov = sigm(g3);
                c = fmaf(fv, c, iv * gv);
                float ot = ov * tanh_acc(c);

                S.ot0s[u] = ot;
                __syncwarp();                    // projection reads own-warp ot only
                const u64* o2 = reinterpret_cast<const u64*>(S.ot0s) + w * 16;
                u64 pA = pk(0.f,0.f), pB = pA;
#pragma unroll
                for (int j = 0; j < 8; j++)  fma2(pA, S.whr0s[w][j][l], o2[j]);
#pragma unroll
                for (int j = 8; j < 16; j++) fma2(pB, S.whr0s[w][j][l], o2[j]);
                S.hp0[w][l] = hsum(add2(pA, pB));
                asm volatile("bar.sync 1, 128;" ::: "memory");
                float hv = (S.hp0[0][l] + S.hp0[1][l]) + (S.hp0[2][l] + S.hp0[3][l]);
                S.hb0[w][l] = hv;                    // own warp's copy for next step
                if (w == 0) S.h0ring[s & 7][l] = hv; // handoff to grp1
                __syncwarp();
            }
        } else if (grp == 1) {
            const int t = i - 4;
            if (t >= 0 && t < T_LEN) {
                const u64* h2 = reinterpret_cast<const u64*>(S.h0ring[t & 7]);
                u64 aA0 = pk(0.f,0.f), aA1 = aA0, aA2 = aA0, aA3 = aA0;
                u64 aB0 = aA0, aB1 = aA0, aB2 = aA0, aB3 = aA0;
#pragma unroll
                for (int j = 0; j < 8; j++) {
                    u64 hv = h2[j];
                    fma2(aA0, wgt[0][j], hv); fma2(aA1, wgt[1][j], hv);
                    fma2(aA2, wgt[2][j], hv); fma2(aA3, wgt[3][j], hv);
                }
#pragma unroll
                for (int j = 8; j < 16; j++) {
                    u64 hv = h2[j];
                    fma2(aB0, wgt[0][j], hv); fma2(aB1, wgt[1][j], hv);
                    fma2(aB2, wgt[2][j], hv); fma2(aB3, wgt[3][j], hv);
                }
                float* xo = S.xi1ring[t & 7];
                xo[u]           = bias1q[0] + hsum(add2(aA0, aB0));
                xo[HID + u]     = bias1q[1] + hsum(add2(aA1, aB1));
                xo[2*HID + u]   = bias1q[2] + hsum(add2(aA2, aB2));
                xo[3*HID + u]   = bias1q[3] + hsum(add2(aA3, aB3));
            }
        } else {
            const int t = i - 8;
            if (t >= 0 && t < T_LEN) {
                const float* xq = S.xi1ring[t & 7];
                float g0 = xq[u],         g1 = xq[HID + u];
                float g2 = xq[2*HID + u], g3 = xq[3*HID + u];
                const u64* h2 = reinterpret_cast<const u64*>(S.hb1[w]);
                u64 aA0 = pk(0.f,0.f), aA1 = aA0, aA2 = aA0, aA3 = aA0;
                u64 aB0 = aA0, aB1 = aA0, aB2 = aA0, aB3 = aA0;
#pragma unroll
                for (int j = 0; j < 8; j++) {
                    u64 hv = h2[j];
                    fma2(aA0, wgt[0][j], hv); fma2(aA1, wgt[1][j], hv);
                    fma2(aA2, wgt[2][j], hv); fma2(aA3, wgt[3][j], hv);
                }
#pragma unroll
                for (int j = 8; j < 16; j++) {
                    u64 hv = h2[j];
                    fma2(aB0, wgt[0][j], hv); fma2(aB1, wgt[1][j], hv);
                    fma2(aB2, wgt[2][j], hv); fma2(aB3, wgt[3][j], hv);
                }
                g0 += hsum(add2(aA0, aB0));
                g1 += hsum(add2(aA1, aB1));
                g2 += hsum(add2(aA2, aB2));
                g3 += hsum(add2(aA3, aB3));

                float iv = sigm(g0), fv = sigm(g1);
                float gv = tanh_acc(g2), ov = sigm(g3);
                c = fmaf(fv, c, iv * gv);
                float ot = ov * tanh_acc(c);

                S.ot1s[u] = ot;
                __syncwarp();                    // projection reads own-warp ot only
                const u64* o2 = reinterpret_cast<const u64*>(S.ot1s) + w * 16;
                u64 pA = pk(0.f,0.f), pB = pA;
#pragma unroll
                for (int j = 0; j < 8; j++)  fma2(pA, S.whr1s[w][j][l], o2[j]);
#pragma unroll
                for (int j = 8; j < 16; j++) fma2(pB, S.whr1s[w][j][l], o2[j]);
                S.hp1[w][l] = hsum(add2(pA, pB));
                asm volatile("bar.sync 2, 128;" ::: "memory");
                float hv = (S.hp1[0][l] + S.hp1[1][l]) + (S.hp1[2][l] + S.hp1[3][l]);
                S.hb1[w][l] = hv;
                if (w == 0) {
                    // head: sigmoid(relu(relu(h1)·W2 + b2))
                    float val = fmaxf(hv, 0.f) * w2v;
#pragma unroll
                    for (int off = 16; off; off >>= 1)
                        val += __shfl_down_sync(0xffffffffu, val, off);
                    if (l == 0) {
                        float z = fmaxf(val + b2v, 0.f);
                        out[(size_t)b * T_LEN + t] = sigm_acc(z);
                    }
                }
                __syncwarp();
            }
        }
        if ((i & 3) == 3) __syncthreads();   // window barrier every 4 steps
    }
}

// ---------------- launch ----------------
extern "C" void kernel_launch(void* const* d_in, const int* in_sizes, int n_in,
                              void* d_out, int out_size)
{
    const float* x    = (const float*)d_in[0];
    const float* Wih0 = (const float*)d_in[1];
    const float* Whh0 = (const float*)d_in[2];
    const float* bih0 = (const float*)d_in[3];
    const float* bhh0 = (const float*)d_in[4];
    const float* Whr0 = (const float*)d_in[5];
    const float* Wih1 = (const float*)d_in[6];
    const float* Whh1 = (const float*)d_in[7];
    const float* bih1 = (const float*)d_in[8];
    const float* bhh1 = (const float*)d_in[9];
    const float* Whr1 = (const float*)d_in[10];
    const float* W2   = (const float*)d_in[11];
    const float* b2   = (const float*)d_in[12];
    float* out = (float*)d_out;

    float* xi;
    cudaGetSymbolAddress((void**)&xi, g_xi);

    const int smemBytes = (int)sizeof(ScanSmem);
    cudaFuncSetAttribute(fused_scan,
                         cudaFuncAttributeMaxDynamicSharedMemorySize, smemBytes);

    dim3 gridG((T_LEN + 127) / 128, BATCH);   // 47 x 64

    gemm_xi0<<<gridG, 512>>>(x, Wih0, bih0, bhh0, xi);
    fused_scan<<<BATCH, 384, smemBytes>>>(xi, Whh0, Whr0,
                                          Wih1, bih1, bhh1, Whh1, Whr1,
                                          W2, b2, out);
}